// round 12
// baseline (speedup 1.0000x reference)
#include <cuda_runtime.h>
#include <cuda_bf16.h>
#include <cuda_fp16.h>
#include <math.h>
#include <stdint.h>

// Problem constants (fixed by the reference)
#define NN 50000
#define EE 1600000
#define FIN 256
#define OUTD 64
#define HEADS 8
#define HO 512   // HEADS*OUTD

// ---------------- device scratch (no allocs allowed) ----------------
__device__ __half g_T16[(size_t)NN * HO];  // transformed nodes + bias, fp16 [N, 512]
__device__ float g_Arx[NN * HEADS];        // exp(Ar + bias_r)
__device__ int   g_cnt[NN];                // zero-init; cycle: count->0->cursor->0 (agg)
__device__ int   g_off[NN + 1];
__device__ int   g_col[EE];
__device__ int   g_part[128];

// ---------------- mma / ldmatrix helpers ----------------
__device__ __forceinline__ void mma_f16(float* d, const uint32_t* a, const uint32_t* b) {
  asm volatile(
      "mma.sync.aligned.m16n8k16.row.col.f32.f16.f16.f32 "
      "{%0,%1,%2,%3}, {%4,%5,%6,%7}, {%8,%9}, {%0,%1,%2,%3};"
      : "+f"(d[0]), "+f"(d[1]), "+f"(d[2]), "+f"(d[3])
      : "r"(a[0]), "r"(a[1]), "r"(a[2]), "r"(a[3]), "r"(b[0]), "r"(b[1]));
}

__device__ __forceinline__ void ldsm_x4(uint32_t* r, uint32_t saddr) {
  asm volatile(
      "ldmatrix.sync.aligned.m8n8.x4.shared.b16 {%0,%1,%2,%3}, [%4];"
      : "=r"(r[0]), "=r"(r[1]), "=r"(r[2]), "=r"(r[3])
      : "r"(saddr));
}

// ---------------- GEMM: T = X (M x 256) * W^T + bias -> fp16, fused exp(Ar) ----------------
// 256 threads, 8 warps (4m x 2n), warp tile 32x64. 2 CTAs/SM. (FROZEN: L1-wavefront
// bound at ~88us; occupancy/prefetch/ldsm variants all neutral.)
#define BM 128
#define BN 128
#define BK 32
#define HPITCH 40   // halves per smem row (80 B pitch; conflict-free for LDS & LDSM)

__global__ __launch_bounds__(256, 2) void gemm_f16_kernel(
    const float* __restrict__ X, const float* __restrict__ W,
    const float* __restrict__ Wb, const float* __restrict__ As,
    const float* __restrict__ As_bias, int M) {
  __shared__ __half sA[BM][HPITCH];
  __shared__ __half sB[BN][HPITCH];
  const int bm = blockIdx.x * BM;
  const int bn = blockIdx.y * BN;
  const int tid = threadIdx.x;
  const int wid = tid >> 5, lane = tid & 31;
  const int wm = (wid & 3) * 32;   // warp m offset
  const int wn = (wid >> 2) * 64;  // warp n offset (one head)
  const int g = lane >> 2;
  const int t = lane & 3;

  const int lrow = lane & 15;
  const int lcol = (lane >> 4) * 8;
  const uint32_t sA_base = (uint32_t)__cvta_generic_to_shared(&sA[0][0]);
  const uint32_t sB_base = (uint32_t)__cvta_generic_to_shared(&sB[0][0]);
  const int aoff = (wm + lrow) * HPITCH + lcol;
  const int boff = (wn + lrow) * HPITCH + lcol;

  float acc[2][8][4];
#pragma unroll
  for (int mt = 0; mt < 2; mt++)
#pragma unroll
    for (int nt = 0; nt < 8; nt++)
#pragma unroll
      for (int j = 0; j < 4; j++) acc[mt][nt][j] = 0.f;

  int srow[4], sc4[4];
  const float* pA[4];
  const float* pB[4];
  bool vA[4];
#pragma unroll
  for (int i = 0; i < 4; i++) {
    int gi = tid + 256 * i;
    srow[i] = gi >> 3;
    sc4[i] = (gi & 7) * 4;
    vA[i] = (bm + srow[i]) < M;
    pA[i] = X + (size_t)(bm + srow[i]) * FIN + sc4[i];
    pB[i] = W + (size_t)(bn + srow[i]) * FIN + sc4[i];
  }

  for (int k0 = 0; k0 < FIN; k0 += BK) {
#pragma unroll
    for (int i = 0; i < 4; i++) {
      float4 va = vA[i] ? *(const float4*)pA[i] : make_float4(0.f, 0.f, 0.f, 0.f);
      float4 vb = *(const float4*)pB[i];
      pA[i] += BK;
      pB[i] += BK;
      __half2 a0 = __floats2half2_rn(va.x, va.y);
      __half2 a1 = __floats2half2_rn(va.z, va.w);
      *(uint2*)&sA[srow[i]][sc4[i]] = make_uint2(*(uint32_t*)&a0, *(uint32_t*)&a1);
      __half2 b0 = __floats2half2_rn(vb.x, vb.y);
      __half2 b1 = __floats2half2_rn(vb.z, vb.w);
      *(uint2*)&sB[srow[i]][sc4[i]] = make_uint2(*(uint32_t*)&b0, *(uint32_t*)&b1);
    }
    __syncthreads();

#pragma unroll
    for (int k16 = 0; k16 < 2; k16++) {
      const int k = k16 * 16;
      uint32_t a[2][4], bb[4][4];
      ldsm_x4(a[0], sA_base + (uint32_t)(aoff + k) * 2);
      ldsm_x4(a[1], sA_base + (uint32_t)(aoff + 16 * HPITCH + k) * 2);
#pragma unroll
      for (int p = 0; p < 4; p++)
        ldsm_x4(bb[p], sB_base + (uint32_t)(boff + p * 16 * HPITCH + k) * 2);
#pragma unroll
      for (int mt = 0; mt < 2; mt++)
#pragma unroll
        for (int p = 0; p < 4; p++) {
          uint32_t b0[2] = {bb[p][0], bb[p][2]};
          uint32_t b1[2] = {bb[p][1], bb[p][3]};
          mma_f16(acc[mt][2 * p], a[mt], b0);
          mma_f16(acc[mt][2 * p + 1], a[mt], b1);
        }
    }
    __syncthreads();
  }

  // ---- epilogue: + Ws_bias (folded into T), store fp16, fused exp(Ar) ----
  const int head = (bn + wn) >> 6;
  float asr[16];
#pragma unroll
  for (int nt = 0; nt < 8; nt++) {
    int colh = nt * 8 + 2 * t;
    asr[nt * 2 + 0] = As[head * 128 + OUTD + colh];
    asr[nt * 2 + 1] = As[head * 128 + OUTD + colh + 1];
  }
  float arsum[4] = {0.f, 0.f, 0.f, 0.f};

#pragma unroll
  for (int mt = 0; mt < 2; mt++) {
    int r0 = bm + wm + mt * 16 + g;
#pragma unroll
    for (int nt = 0; nt < 8; nt++) {
      int c = bn + wn + nt * 8 + 2 * t;
      float wb0 = Wb[c], wb1 = Wb[c + 1];
      float v0 = acc[mt][nt][0] + wb0, v1 = acc[mt][nt][1] + wb1;
      float v2 = acc[mt][nt][2] + wb0, v3 = acc[mt][nt][3] + wb1;
      arsum[mt * 2 + 0] += v0 * asr[nt * 2] + v1 * asr[nt * 2 + 1];
      arsum[mt * 2 + 1] += v2 * asr[nt * 2] + v3 * asr[nt * 2 + 1];
      if (r0 < M)
        *(__half2*)&g_T16[(size_t)r0 * HO + c] = __floats2half2_rn(v0, v1);
      if (r0 + 8 < M)
        *(__half2*)&g_T16[(size_t)(r0 + 8) * HO + c] = __floats2half2_rn(v2, v3);
    }
  }
  float bias_r = As_bias[head * 2 + 1];
#pragma unroll
  for (int q = 0; q < 4; q++) {
    float v = arsum[q];
    v += __shfl_xor_sync(0xffffffffu, v, 1);
    v += __shfl_xor_sync(0xffffffffu, v, 2);
    if (t == 0) {
      int r = bm + wm + (q >> 1) * 16 + g + (q & 1) * 8;
      if (r < M) g_Arx[r * HEADS + head] = __expf(v + bias_r);
    }
  }
}

// ---------------- CSR build ----------------
__global__ void count_kernel(const int* __restrict__ row, int E) {
  int e = blockIdx.x * blockDim.x + threadIdx.x;
  if (e < E) atomicAdd(&g_cnt[row[e]], 1);
}

__global__ __launch_bounds__(1024) void scan_blocks_kernel(int N) {
  __shared__ int warpsum[32];
  int tid = threadIdx.x, lane = tid & 31, w = tid >> 5;
  int i = blockIdx.x * 1024 + tid;
  int v = (i < N) ? g_cnt[i] : 0;
#pragma unroll
  for (int o = 1; o < 32; o <<= 1) {
    int u = __shfl_up_sync(0xffffffffu, v, o);
    if (lane >= o) v += u;
  }
  if (lane == 31) warpsum[w] = v;
  __syncthreads();
  if (w == 0) {
    int s = warpsum[lane];
#pragma unroll
    for (int o = 1; o < 32; o <<= 1) {
      int u = __shfl_up_sync(0xffffffffu, s, o);
      if (lane >= o) s += u;
    }
    warpsum[lane] = s;
    if (lane == 31) g_part[blockIdx.x] = s;
  }
  __syncthreads();
  int add = (w > 0) ? warpsum[w - 1] : 0;
  if (i < N) g_off[i + 1] = v + add;
}

__global__ void scan_part_kernel(int nb) {
  int lane = threadIdx.x;
  if (lane == 0) g_off[0] = 0;
  int carry = 0;
  for (int base = 0; base < nb; base += 32) {
    int v = (base + lane < nb) ? g_part[base + lane] : 0;
    int inc = v;
#pragma unroll
    for (int o = 1; o < 32; o <<= 1) {
      int u = __shfl_up_sync(0xffffffffu, inc, o);
      if (lane >= o) inc += u;
    }
    if (base + lane < nb) g_part[base + lane] = carry + inc - v;
    carry += __shfl_sync(0xffffffffu, inc, 31);
  }
}

__global__ void scan_add_kernel(int N) {
  int i = blockIdx.x * blockDim.x + threadIdx.x;
  if (i < N) {
    g_off[i + 1] += g_part[i >> 10];
    g_cnt[i] = 0;  // zero cursors for scatter
  }
}

__global__ void scatter_kernel(const int* __restrict__ row,
                               const int* __restrict__ col, int E) {
  int e = blockIdx.x * blockDim.x + threadIdx.x;
  if (e < E) {
    int r = row[e];
    int p = atomicAdd(&g_cnt[r], 1);
    g_col[g_off[r] + p] = col[e];
  }
}

// ---------------- aggregate: softmax over incoming edges + weighted gather ----------------
// One block/node, warp h = head h. exp precomputed (g_Arx). Pass C: 4 edges per
// warp iteration — 8 lanes per edge, uint4 (16 B) per lane = full 128-B slice;
// one LDS.64 + one LDG.128 per lane per 4 edges. Remainder via lane-quarter predication.
#define SMAX 256
__global__ __launch_bounds__(256) void agg_kernel(
    const float* __restrict__ Wb, float* __restrict__ out, int N) {
  int n = blockIdx.x;
  int tid = threadIdx.x;
  int h = tid >> 5, l = tid & 31;
  int quarter = l >> 3, ql = l & 7;
  int s = g_off[n];
  int deg = g_off[n + 1] - s;
  if (tid == 0) g_cnt[n] = 0;  // reset for next replay's count_kernel

  __shared__ float2 sfe[SMAX * 9];  // [i][h]: (exp(score), T-row byte offset)

  float acc8[8] = {0.f, 0.f, 0.f, 0.f, 0.f, 0.f, 0.f, 0.f};
  float inv = 0.f;

  if (deg > 0 && deg <= SMAX) {
    // pass A: coalesced exp load + byte offset
    int tot = deg * 8;
    for (int idx = tid; idx < tot; idx += 256) {
      int i = idx >> 3, hh = idx & 7;
      int c = g_col[s + i];
      sfe[i * 9 + hh] = make_float2(g_Arx[c * HEADS + hh], __int_as_float(c * (HO * 2)));
    }
    __syncthreads();

    // pass B: per-head sum of unnormalized alpha
    float sum = 0.f;
    for (int i = l; i < deg; i += 32) sum += sfe[i * 9 + h].x;
#pragma unroll
    for (int o = 16; o; o >>= 1) sum += __shfl_xor_sync(0xffffffffu, sum, o);
    inv = 1.f / sum;

    // pass C: 4 edges / iteration; this lane covers 8 cols (16 B) of its edge
    const char* Tb = (const char*)g_T16 + (size_t)h * 128 + (size_t)ql * 16;
    int deg4 = deg & ~3;
#pragma unroll 4
    for (int i = 0; i < deg4; i += 4) {
      float2 fc = sfe[(i + quarter) * 9 + h];
      uint4 raw = *(const uint4*)(Tb + __float_as_int(fc.y));
      float2 f0 = __half22float2(*(__half2*)&raw.x);
      float2 f1 = __half22float2(*(__half2*)&raw.y);
      float2 f2 = __half22float2(*(__half2*)&raw.z);
      float2 f3 = __half22float2(*(__half2*)&raw.w);
      acc8[0] += fc.x * f0.x; acc8[1] += fc.x * f0.y;
      acc8[2] += fc.x * f1.x; acc8[3] += fc.x * f1.y;
      acc8[4] += fc.x * f2.x; acc8[5] += fc.x * f2.y;
      acc8[6] += fc.x * f3.x; acc8[7] += fc.x * f3.y;
    }
    int rem = deg - deg4;
    if (quarter < rem) {
      float2 fc = sfe[(deg4 + quarter) * 9 + h];
      uint4 raw = *(const uint4*)(Tb + __float_as_int(fc.y));
      float2 f0 = __half22float2(*(__half2*)&raw.x);
      float2 f1 = __half22float2(*(__half2*)&raw.y);
      float2 f2 = __half22float2(*(__half2*)&raw.z);
      float2 f3 = __half22float2(*(__half2*)&raw.w);
      acc8[0] += fc.x * f0.x; acc8[1] += fc.x * f0.y;
      acc8[2] += fc.x * f1.x; acc8[3] += fc.x * f1.y;
      acc8[4] += fc.x * f2.x; acc8[5] += fc.x * f2.y;
      acc8[6] += fc.x * f3.x; acc8[7] += fc.x * f3.y;
    }
  } else if (deg > SMAX) {
    // fallback for huge degree: stream from global, exps precomputed
    float sum = 0.f;
    for (int i = l; i < deg; i += 32)
      sum += g_Arx[g_col[s + i] * HEADS + h];
#pragma unroll
    for (int o = 16; o; o >>= 1) sum += __shfl_xor_sync(0xffffffffu, sum, o);
    inv = 1.f / sum;
    const char* Tb = (const char*)g_T16 + (size_t)h * 128 + (size_t)ql * 16;
    int deg4 = deg & ~3;
    for (int i = 0; i < deg4; i += 4) {
      int c = g_col[s + i + quarter];
      float a = g_Arx[c * HEADS + h];
      uint4 raw = *(const uint4*)(Tb + (size_t)c * (HO * 2));
      float2 f0 = __half22float2(*(__half2*)&raw.x);
      float2 f1 = __half22float2(*(__half2*)&raw.y);
      float2 f2 = __half22float2(*(__half2*)&raw.z);
      float2 f3 = __half22float2(*(__half2*)&raw.w);
      acc8[0] += a * f0.x; acc8[1] += a * f0.y;
      acc8[2] += a * f1.x; acc8[3] += a * f1.y;
      acc8[4] += a * f2.x; acc8[5] += a * f2.y;
      acc8[6] += a * f3.x; acc8[7] += a * f3.y;
    }
    int rem = deg - deg4;
    if (quarter < rem) {
      int c = g_col[s + deg4 + quarter];
      float a = g_Arx[c * HEADS + h];
      uint4 raw = *(const uint4*)(Tb + (size_t)c * (HO * 2));
      float2 f0 = __half22float2(*(__half2*)&raw.x);
      float2 f1 = __half22float2(*(__half2*)&raw.y);
      float2 f2 = __half22float2(*(__half2*)&raw.z);
      float2 f3 = __half22float2(*(__half2*)&raw.w);
      acc8[0] += a * f0.x; acc8[1] += a * f0.y;
      acc8[2] += a * f1.x; acc8[3] += a * f1.y;
      acc8[4] += a * f2.x; acc8[5] += a * f2.y;
      acc8[6] += a * f3.x; acc8[7] += a * f3.y;
    }
  }

  // combine the four lane-quarters; lanes 0-7 of each warp store 8 cols
#pragma unroll
  for (int j = 0; j < 8; j++) {
    acc8[j] += __shfl_xor_sync(0xffffffffu, acc8[j], 8);
    acc8[j] += __shfl_xor_sync(0xffffffffu, acc8[j], 16);
  }
  if (quarter == 0) {
    int oc = h * 64 + 8 * ql;
    float r[8];
    if (deg == 0) {  // T carries Ws_bias and sum(alpha)=1 otherwise
#pragma unroll
      for (int j = 0; j < 8; j++) r[j] = Wb[oc + j];
    } else {
#pragma unroll
      for (int j = 0; j < 8; j++) r[j] = acc8[j] * inv;
    }
#pragma unroll
    for (int j = 0; j < 8; j++) r[j] = r[j] > 0.f ? r[j] : expm1f(r[j]);
    float4 v0 = make_float4(r[0], r[1], r[2], r[3]);
    float4 v1 = make_float4(r[4], r[5], r[6], r[7]);
    *(float4*)(out + (size_t)n * HO + oc) = v0;
    *(float4*)(out + (size_t)n * HO + oc + 4) = v1;
  }
}

// ---------------- launch ----------------
extern "C" void kernel_launch(void* const* d_in, const int* in_sizes, int n_in,
                              void* d_out, int out_size) {
  const float* x        = (const float*)d_in[0];
  const int*   edge_row = (const int*)d_in[1];
  const int*   edge_col = (const int*)d_in[2];
  const float* Ws       = (const float*)d_in[3];
  const float* Ws_bias  = (const float*)d_in[4];
  const float* As       = (const float*)d_in[5];
  const float* As_bias  = (const float*)d_in[6];
  float* out = (float*)d_out;

  const int N = in_sizes[0] / FIN;   // 50000
  const int E = in_sizes[1];         // 1600000

  // one-time stream/event setup (host objects only; no device memory)
  static cudaStream_t s2 = nullptr;
  static cudaEvent_t ev_fork = nullptr, ev_join = nullptr;
  if (s2 == nullptr) {
    cudaStreamCreateWithFlags(&s2, cudaStreamNonBlocking);
    cudaEventCreateWithFlags(&ev_fork, cudaEventDisableTiming);
    cudaEventCreateWithFlags(&ev_join, cudaEventDisableTiming);
  }

  int eb = (E + 255) / 256;
  int nb = (N + 1023) / 1024;

  // fork: CSR build on s2, concurrent with GEMM on the capture stream
  cudaEventRecord(ev_fork, 0);
  cudaStreamWaitEvent(s2, ev_fork, 0);
  count_kernel<<<eb, 256, 0, s2>>>(edge_row, E);
  scan_blocks_kernel<<<nb, 1024, 0, s2>>>(N);
  scan_part_kernel<<<1, 32, 0, s2>>>(nb);

  // main stream: GEMM (4th submission -> profiled by ncu)
  dim3 ggrid((N + BM - 1) / BM, HO / BN);
  gemm_f16_kernel<<<ggrid, 256>>>(x, Ws, Ws_bias, As, As_bias, N);

  scan_add_kernel<<<(N + 255) / 256, 256, 0, s2>>>(N);
  scatter_kernel<<<eb, 256, 0, s2>>>(edge_row, edge_col, E);
  cudaEventRecord(ev_join, s2);

  // join, then softmax + aggregate + ELU
  cudaStreamWaitEvent(0, ev_join, 0);
  agg_kernel<<<N, 256>>>(Ws_bias, out, N);
}

// round 13
// speedup vs baseline: 1.2182x; 1.2182x over previous
#include <cuda_runtime.h>
#include <cuda_bf16.h>
#include <cuda_fp16.h>
#include <math.h>
#include <stdint.h>

// Problem constants (fixed by the reference)
#define NN 50000
#define EE 1600000
#define FIN 256
#define OUTD 64
#define HEADS 8
#define HO 512   // HEADS*OUTD

// ---------------- device scratch (no allocs allowed) ----------------
__device__ __half g_T16[(size_t)NN * HO];  // transformed nodes + bias, fp16 [N, 512]
__device__ float g_Arx[NN * HEADS];        // exp(Ar + bias_r)
__device__ int   g_cnt[NN];                // zero-init; cycle: count->0->cursor->0 (agg)
__device__ int   g_off[NN + 1];
__device__ int   g_col[EE];
__device__ int   g_part[128];

// ---------------- mma / ldmatrix helpers ----------------
__device__ __forceinline__ void mma_f16(float* d, const uint32_t* a, const uint32_t* b) {
  asm volatile(
      "mma.sync.aligned.m16n8k16.row.col.f32.f16.f16.f32 "
      "{%0,%1,%2,%3}, {%4,%5,%6,%7}, {%8,%9}, {%0,%1,%2,%3};"
      : "+f"(d[0]), "+f"(d[1]), "+f"(d[2]), "+f"(d[3])
      : "r"(a[0]), "r"(a[1]), "r"(a[2]), "r"(a[3]), "r"(b[0]), "r"(b[1]));
}

__device__ __forceinline__ void ldsm_x4(uint32_t* r, uint32_t saddr) {
  asm volatile(
      "ldmatrix.sync.aligned.m8n8.x4.shared.b16 {%0,%1,%2,%3}, [%4];"
      : "=r"(r[0]), "=r"(r[1]), "=r"(r[2]), "=r"(r[3])
      : "r"(saddr));
}

// ---------------- GEMM: T = X (M x 256) * W^T + bias -> fp16, fused exp(Ar) ----------------
// 256 threads, 8 warps (4m x 2n), warp tile 32x64. 2 CTAs/SM. (FROZEN: L1-wavefront
// bound at ~88us; occupancy/prefetch/ldsm variants all neutral.)
#define BM 128
#define BN 128
#define BK 32
#define HPITCH 40   // halves per smem row (80 B pitch; conflict-free for LDS & LDSM)

__global__ __launch_bounds__(256, 2) void gemm_f16_kernel(
    const float* __restrict__ X, const float* __restrict__ W,
    const float* __restrict__ Wb, const float* __restrict__ As,
    const float* __restrict__ As_bias, int M) {
  __shared__ __half sA[BM][HPITCH];
  __shared__ __half sB[BN][HPITCH];
  const int bm = blockIdx.x * BM;
  const int bn = blockIdx.y * BN;
  const int tid = threadIdx.x;
  const int wid = tid >> 5, lane = tid & 31;
  const int wm = (wid & 3) * 32;   // warp m offset
  const int wn = (wid >> 2) * 64;  // warp n offset (one head)
  const int g = lane >> 2;
  const int t = lane & 3;

  const int lrow = lane & 15;
  const int lcol = (lane >> 4) * 8;
  const uint32_t sA_base = (uint32_t)__cvta_generic_to_shared(&sA[0][0]);
  const uint32_t sB_base = (uint32_t)__cvta_generic_to_shared(&sB[0][0]);
  const int aoff = (wm + lrow) * HPITCH + lcol;
  const int boff = (wn + lrow) * HPITCH + lcol;

  float acc[2][8][4];
#pragma unroll
  for (int mt = 0; mt < 2; mt++)
#pragma unroll
    for (int nt = 0; nt < 8; nt++)
#pragma unroll
      for (int j = 0; j < 4; j++) acc[mt][nt][j] = 0.f;

  int srow[4], sc4[4];
  const float* pA[4];
  const float* pB[4];
  bool vA[4];
#pragma unroll
  for (int i = 0; i < 4; i++) {
    int gi = tid + 256 * i;
    srow[i] = gi >> 3;
    sc4[i] = (gi & 7) * 4;
    vA[i] = (bm + srow[i]) < M;
    pA[i] = X + (size_t)(bm + srow[i]) * FIN + sc4[i];
    pB[i] = W + (size_t)(bn + srow[i]) * FIN + sc4[i];
  }

  for (int k0 = 0; k0 < FIN; k0 += BK) {
#pragma unroll
    for (int i = 0; i < 4; i++) {
      float4 va = vA[i] ? *(const float4*)pA[i] : make_float4(0.f, 0.f, 0.f, 0.f);
      float4 vb = *(const float4*)pB[i];
      pA[i] += BK;
      pB[i] += BK;
      __half2 a0 = __floats2half2_rn(va.x, va.y);
      __half2 a1 = __floats2half2_rn(va.z, va.w);
      *(uint2*)&sA[srow[i]][sc4[i]] = make_uint2(*(uint32_t*)&a0, *(uint32_t*)&a1);
      __half2 b0 = __floats2half2_rn(vb.x, vb.y);
      __half2 b1 = __floats2half2_rn(vb.z, vb.w);
      *(uint2*)&sB[srow[i]][sc4[i]] = make_uint2(*(uint32_t*)&b0, *(uint32_t*)&b1);
    }
    __syncthreads();

#pragma unroll
    for (int k16 = 0; k16 < 2; k16++) {
      const int k = k16 * 16;
      uint32_t a[2][4], bb[4][4];
      ldsm_x4(a[0], sA_base + (uint32_t)(aoff + k) * 2);
      ldsm_x4(a[1], sA_base + (uint32_t)(aoff + 16 * HPITCH + k) * 2);
#pragma unroll
      for (int p = 0; p < 4; p++)
        ldsm_x4(bb[p], sB_base + (uint32_t)(boff + p * 16 * HPITCH + k) * 2);
#pragma unroll
      for (int mt = 0; mt < 2; mt++)
#pragma unroll
        for (int p = 0; p < 4; p++) {
          uint32_t b0[2] = {bb[p][0], bb[p][2]};
          uint32_t b1[2] = {bb[p][1], bb[p][3]};
          mma_f16(acc[mt][2 * p], a[mt], b0);
          mma_f16(acc[mt][2 * p + 1], a[mt], b1);
        }
    }
    __syncthreads();
  }

  // ---- epilogue: + Ws_bias (folded into T), store fp16, fused exp(Ar) ----
  const int head = (bn + wn) >> 6;
  float asr[16];
#pragma unroll
  for (int nt = 0; nt < 8; nt++) {
    int colh = nt * 8 + 2 * t;
    asr[nt * 2 + 0] = As[head * 128 + OUTD + colh];
    asr[nt * 2 + 1] = As[head * 128 + OUTD + colh + 1];
  }
  float arsum[4] = {0.f, 0.f, 0.f, 0.f};

#pragma unroll
  for (int mt = 0; mt < 2; mt++) {
    int r0 = bm + wm + mt * 16 + g;
#pragma unroll
    for (int nt = 0; nt < 8; nt++) {
      int c = bn + wn + nt * 8 + 2 * t;
      float wb0 = Wb[c], wb1 = Wb[c + 1];
      float v0 = acc[mt][nt][0] + wb0, v1 = acc[mt][nt][1] + wb1;
      float v2 = acc[mt][nt][2] + wb0, v3 = acc[mt][nt][3] + wb1;
      arsum[mt * 2 + 0] += v0 * asr[nt * 2] + v1 * asr[nt * 2 + 1];
      arsum[mt * 2 + 1] += v2 * asr[nt * 2] + v3 * asr[nt * 2 + 1];
      if (r0 < M)
        *(__half2*)&g_T16[(size_t)r0 * HO + c] = __floats2half2_rn(v0, v1);
      if (r0 + 8 < M)
        *(__half2*)&g_T16[(size_t)(r0 + 8) * HO + c] = __floats2half2_rn(v2, v3);
    }
  }
  float bias_r = As_bias[head * 2 + 1];
#pragma unroll
  for (int q = 0; q < 4; q++) {
    float v = arsum[q];
    v += __shfl_xor_sync(0xffffffffu, v, 1);
    v += __shfl_xor_sync(0xffffffffu, v, 2);
    if (t == 0) {
      int r = bm + wm + (q >> 1) * 16 + g + (q & 1) * 8;
      if (r < M) g_Arx[r * HEADS + head] = __expf(v + bias_r);
    }
  }
}

// ---------------- CSR build ----------------
__global__ void count_kernel(const int* __restrict__ row, int E) {
  int e = blockIdx.x * blockDim.x + threadIdx.x;
  if (e < E) atomicAdd(&g_cnt[row[e]], 1);
}

__global__ __launch_bounds__(1024) void scan_blocks_kernel(int N) {
  __shared__ int warpsum[32];
  int tid = threadIdx.x, lane = tid & 31, w = tid >> 5;
  int i = blockIdx.x * 1024 + tid;
  int v = (i < N) ? g_cnt[i] : 0;
#pragma unroll
  for (int o = 1; o < 32; o <<= 1) {
    int u = __shfl_up_sync(0xffffffffu, v, o);
    if (lane >= o) v += u;
  }
  if (lane == 31) warpsum[w] = v;
  __syncthreads();
  if (w == 0) {
    int s = warpsum[lane];
#pragma unroll
    for (int o = 1; o < 32; o <<= 1) {
      int u = __shfl_up_sync(0xffffffffu, s, o);
      if (lane >= o) s += u;
    }
    warpsum[lane] = s;
    if (lane == 31) g_part[blockIdx.x] = s;
  }
  __syncthreads();
  int add = (w > 0) ? warpsum[w - 1] : 0;
  if (i < N) g_off[i + 1] = v + add;
}

__global__ void scan_part_kernel(int nb) {
  int lane = threadIdx.x;
  if (lane == 0) g_off[0] = 0;
  int carry = 0;
  for (int base = 0; base < nb; base += 32) {
    int v = (base + lane < nb) ? g_part[base + lane] : 0;
    int inc = v;
#pragma unroll
    for (int o = 1; o < 32; o <<= 1) {
      int u = __shfl_up_sync(0xffffffffu, inc, o);
      if (lane >= o) inc += u;
    }
    if (base + lane < nb) g_part[base + lane] = carry + inc - v;
    carry += __shfl_sync(0xffffffffu, inc, 31);
  }
}

__global__ void scan_add_kernel(int N) {
  int i = blockIdx.x * blockDim.x + threadIdx.x;
  if (i < N) {
    g_off[i + 1] += g_part[i >> 10];
    g_cnt[i] = 0;  // zero cursors for scatter
  }
}

__global__ void scatter_kernel(const int* __restrict__ row,
                               const int* __restrict__ col, int E) {
  int e = blockIdx.x * blockDim.x + threadIdx.x;
  if (e < E) {
    int r = row[e];
    int p = atomicAdd(&g_cnt[r], 1);
    g_col[g_off[r] + p] = col[e];
  }
}

// ---------------- aggregate: softmax over incoming edges + weighted gather ----------------
// One block/node, warp h = head h. exp precomputed (g_Arx). Pass C: 2 edges per
// warp iteration (lanes 0-15 edge i, lanes 16-31 edge i+1, uint2/lane), unroll 8.
// (r11-proven structure; r12's 4-edge LDG.128 variant regressed — wavefront count
// is per-line, so wider loads saved nothing and added tail/combine overhead.)
#define SMAX 256
__global__ __launch_bounds__(256) void agg_kernel(
    const float* __restrict__ Wb, float* __restrict__ out, int N) {
  int n = blockIdx.x;
  int tid = threadIdx.x;
  int h = tid >> 5, l = tid & 31;
  int half = l >> 4, sl = l & 15;
  int s = g_off[n];
  int deg = g_off[n + 1] - s;
  if (tid == 0) g_cnt[n] = 0;  // reset for next replay's count_kernel

  __shared__ float2 sfe[SMAX * 9];  // [i][h]: (exp(score), T-row byte offset)

  float acc4[4] = {0.f, 0.f, 0.f, 0.f};
  float inv = 0.f;

  if (deg > 0 && deg <= SMAX) {
    // pass A: coalesced exp load + byte offset
    int tot = deg * 8;
    for (int idx = tid; idx < tot; idx += 256) {
      int i = idx >> 3, hh = idx & 7;
      int c = g_col[s + i];
      sfe[i * 9 + hh] = make_float2(g_Arx[c * HEADS + hh], __int_as_float(c * (HO * 2)));
    }
    __syncthreads();

    // pass B: per-head sum of unnormalized alpha
    float sum = 0.f;
    for (int i = l; i < deg; i += 32) sum += sfe[i * 9 + h].x;
#pragma unroll
    for (int o = 16; o; o >>= 1) sum += __shfl_xor_sync(0xffffffffu, sum, o);
    inv = 1.f / sum;

    // pass C: 2 edges per iteration; lane covers 4 cols (8 B) of its edge's slice
    const char* Tb = (const char*)g_T16 + (size_t)h * 128 + (size_t)sl * 8;
    int deg2 = deg & ~1;
#pragma unroll 8
    for (int i = 0; i < deg2; i += 2) {
      float2 fc = sfe[(i + half) * 9 + h];
      uint2 raw = *(const uint2*)(Tb + __float_as_int(fc.y));
      float2 f0 = __half22float2(*(__half2*)&raw.x);
      float2 f1 = __half22float2(*(__half2*)&raw.y);
      acc4[0] += fc.x * f0.x;
      acc4[1] += fc.x * f0.y;
      acc4[2] += fc.x * f1.x;
      acc4[3] += fc.x * f1.y;
    }
    if (deg & 1) {
      float2 fc = sfe[deg2 * 9 + h];
      if (half == 0) {
        uint2 raw = *(const uint2*)(Tb + __float_as_int(fc.y));
        float2 f0 = __half22float2(*(__half2*)&raw.x);
        float2 f1 = __half22float2(*(__half2*)&raw.y);
        acc4[0] += fc.x * f0.x;
        acc4[1] += fc.x * f0.y;
        acc4[2] += fc.x * f1.x;
        acc4[3] += fc.x * f1.y;
      }
    }
  } else if (deg > SMAX) {
    // fallback for huge degree: stream from global, exps precomputed
    float sum = 0.f;
    for (int i = l; i < deg; i += 32)
      sum += g_Arx[g_col[s + i] * HEADS + h];
#pragma unroll
    for (int o = 16; o; o >>= 1) sum += __shfl_xor_sync(0xffffffffu, sum, o);
    inv = 1.f / sum;
    const char* Tb = (const char*)g_T16 + (size_t)h * 128 + (size_t)sl * 8;
    int deg2 = deg & ~1;
    for (int i = 0; i < deg2; i += 2) {
      int c = g_col[s + i + half];
      float a = g_Arx[c * HEADS + h];
      uint2 raw = *(const uint2*)(Tb + (size_t)c * (HO * 2));
      float2 f0 = __half22float2(*(__half2*)&raw.x);
      float2 f1 = __half22float2(*(__half2*)&raw.y);
      acc4[0] += a * f0.x;
      acc4[1] += a * f0.y;
      acc4[2] += a * f1.x;
      acc4[3] += a * f1.y;
    }
    if (deg & 1) {
      int c = g_col[s + deg2];
      float a = g_Arx[c * HEADS + h];
      if (half == 0) {
        uint2 raw = *(const uint2*)(Tb + (size_t)c * (HO * 2));
        float2 f0 = __half22float2(*(__half2*)&raw.x);
        float2 f1 = __half22float2(*(__half2*)&raw.y);
        acc4[0] += a * f0.x;
        acc4[1] += a * f0.y;
        acc4[2] += a * f1.x;
        acc4[3] += a * f1.y;
      }
    }
  }

  // combine the two lane-halves; lanes 0-15 of each warp store 4 cols
#pragma unroll
  for (int j = 0; j < 4; j++) acc4[j] += __shfl_xor_sync(0xffffffffu, acc4[j], 16);
  if (half == 0) {
    int oc = h * 64 + 4 * sl;
    float4 r;
    if (deg == 0) {  // T carries Ws_bias and sum(alpha)=1 otherwise
      r.x = Wb[oc]; r.y = Wb[oc + 1]; r.z = Wb[oc + 2]; r.w = Wb[oc + 3];
    } else {
      r.x = acc4[0] * inv; r.y = acc4[1] * inv; r.z = acc4[2] * inv; r.w = acc4[3] * inv;
    }
    r.x = r.x > 0.f ? r.x : expm1f(r.x);
    r.y = r.y > 0.f ? r.y : expm1f(r.y);
    r.z = r.z > 0.f ? r.z : expm1f(r.z);
    r.w = r.w > 0.f ? r.w : expm1f(r.w);
    *(float4*)(out + (size_t)n * HO + oc) = r;
  }
}

// ---------------- launch ----------------
extern "C" void kernel_launch(void* const* d_in, const int* in_sizes, int n_in,
                              void* d_out, int out_size) {
  const float* x        = (const float*)d_in[0];
  const int*   edge_row = (const int*)d_in[1];
  const int*   edge_col = (const int*)d_in[2];
  const float* Ws       = (const float*)d_in[3];
  const float* Ws_bias  = (const float*)d_in[4];
  const float* As       = (const float*)d_in[5];
  const float* As_bias  = (const float*)d_in[6];
  float* out = (float*)d_out;

  const int N = in_sizes[0] / FIN;   // 50000
  const int E = in_sizes[1];         // 1600000

  // one-time stream/event setup (host objects only; no device memory)
  static cudaStream_t s2 = nullptr;
  static cudaEvent_t ev_fork = nullptr, ev_join = nullptr;
  if (s2 == nullptr) {
    cudaStreamCreateWithFlags(&s2, cudaStreamNonBlocking);
    cudaEventCreateWithFlags(&ev_fork, cudaEventDisableTiming);
    cudaEventCreateWithFlags(&ev_join, cudaEventDisableTiming);
  }

  int eb = (E + 255) / 256;
  int nb = (N + 1023) / 1024;

  // fork: CSR build on s2, concurrent with GEMM on the capture stream
  cudaEventRecord(ev_fork, 0);
  cudaStreamWaitEvent(s2, ev_fork, 0);
  count_kernel<<<eb, 256, 0, s2>>>(edge_row, E);
  scan_blocks_kernel<<<nb, 1024, 0, s2>>>(N);
  scan_part_kernel<<<1, 32, 0, s2>>>(nb);

  // main stream: GEMM (4th submission -> profiled by ncu)
  dim3 ggrid((N + BM - 1) / BM, HO / BN);
  gemm_f16_kernel<<<ggrid, 256>>>(x, Ws, Ws_bias, As, As_bias, N);

  scan_add_kernel<<<(N + 255) / 256, 256, 0, s2>>>(N);
  scatter_kernel<<<eb, 256, 0, s2>>>(edge_row, edge_col, E);
  cudaEventRecord(ev_join, s2);

  // join, then softmax + aggregate + ELU
  cudaStreamWaitEvent(0, ev_join, 0);
  agg_kernel<<<N, 256>>>(Ws_bias, out, N);
}

// round 15
// speedup vs baseline: 1.2716x; 1.0438x over previous
#include <cuda_runtime.h>
#include <cuda_bf16.h>
#include <cuda_fp16.h>
#include <math.h>
#include <stdint.h>

// Problem constants (fixed by the reference)
#define NN 50000
#define EE 1600000
#define FIN 256
#define OUTD 64
#define HEADS 8
#define HO 512   // HEADS*OUTD

// ---------------- device scratch (no allocs allowed) ----------------
__device__ __half g_T16[(size_t)NN * HO];  // transformed nodes + bias, fp16 [N, 512]
__device__ float g_Arx[NN * HEADS];        // exp(Ar + bias_r)
__device__ int   g_cnt[NN];                // zero-init; cycle: count->0->cursor->0 (agg)
__device__ int   g_off[NN + 1];
__device__ int   g_col[EE];
__device__ int   g_part[128];

// ---------------- mma / ldmatrix / cache-hint helpers ----------------
__device__ __forceinline__ void mma_f16(float* d, const uint32_t* a, const uint32_t* b) {
  asm volatile(
      "mma.sync.aligned.m16n8k16.row.col.f32.f16.f16.f32 "
      "{%0,%1,%2,%3}, {%4,%5,%6,%7}, {%8,%9}, {%0,%1,%2,%3};"
      : "+f"(d[0]), "+f"(d[1]), "+f"(d[2]), "+f"(d[3])
      : "r"(a[0]), "r"(a[1]), "r"(a[2]), "r"(a[3]), "r"(b[0]), "r"(b[1]));
}

__device__ __forceinline__ void ldsm_x4(uint32_t* r, uint32_t saddr) {
  asm volatile(
      "ldmatrix.sync.aligned.m8n8.x4.shared.b16 {%0,%1,%2,%3}, [%4];"
      : "=r"(r[0]), "=r"(r[1]), "=r"(r[2]), "=r"(r[3])
      : "r"(saddr));
}

// access policy: evict_last for the whole allocation fraction
__device__ __forceinline__ uint64_t mk_policy_el() {
  uint64_t p;
  asm("createpolicy.fractional.L2::evict_last.b64 %0, 1.0;" : "=l"(p));
  return p;
}

// T gather load: keep T lines resident in L2 (evict_last via cache_hint)
__device__ __forceinline__ uint2 ldg_T_el(const void* p, uint64_t pol) {
  uint2 v;
  asm volatile("ld.global.nc.L2::cache_hint.v2.u32 {%0,%1}, [%2], %3;"
               : "=r"(v.x), "=r"(v.y) : "l"(p), "l"(pol));
  return v;
}

// T creation store: born L2-resident
__device__ __forceinline__ void stg_T_el(void* p, uint32_t v, uint64_t pol) {
  asm volatile("st.global.L2::cache_hint.b32 [%0], %1, %2;"
               :: "l"(p), "r"(v), "l"(pol) : "memory");
}

// output store: streaming (evict-first), don't pollute L2
__device__ __forceinline__ void stg_out_cs(void* p, float4 v) {
  asm volatile("st.global.cs.v4.f32 [%0], {%1,%2,%3,%4};"
               :: "l"(p), "f"(v.x), "f"(v.y), "f"(v.z), "f"(v.w) : "memory");
}

// ---------------- GEMM: T = X (M x 256) * W^T + bias -> fp16, fused exp(Ar) ----------------
// 256 threads, 8 warps (4m x 2n), warp tile 32x64. 2 CTAs/SM. (FROZEN structure:
// L1-wavefront bound at ~88us; only store cache-hint changed vs r11.)
#define BM 128
#define BN 128
#define BK 32
#define HPITCH 40   // halves per smem row (80 B pitch; conflict-free for LDS & LDSM)

__global__ __launch_bounds__(256, 2) void gemm_f16_kernel(
    const float* __restrict__ X, const float* __restrict__ W,
    const float* __restrict__ Wb, const float* __restrict__ As,
    const float* __restrict__ As_bias, int M) {
  __shared__ __half sA[BM][HPITCH];
  __shared__ __half sB[BN][HPITCH];
  const int bm = blockIdx.x * BM;
  const int bn = blockIdx.y * BN;
  const int tid = threadIdx.x;
  const int wid = tid >> 5, lane = tid & 31;
  const int wm = (wid & 3) * 32;   // warp m offset
  const int wn = (wid >> 2) * 64;  // warp n offset (one head)
  const int g = lane >> 2;
  const int t = lane & 3;

  const int lrow = lane & 15;
  const int lcol = (lane >> 4) * 8;
  const uint32_t sA_base = (uint32_t)__cvta_generic_to_shared(&sA[0][0]);
  const uint32_t sB_base = (uint32_t)__cvta_generic_to_shared(&sB[0][0]);
  const int aoff = (wm + lrow) * HPITCH + lcol;
  const int boff = (wn + lrow) * HPITCH + lcol;

  float acc[2][8][4];
#pragma unroll
  for (int mt = 0; mt < 2; mt++)
#pragma unroll
    for (int nt = 0; nt < 8; nt++)
#pragma unroll
      for (int j = 0; j < 4; j++) acc[mt][nt][j] = 0.f;

  int srow[4], sc4[4];
  const float* pA[4];
  const float* pB[4];
  bool vA[4];
#pragma unroll
  for (int i = 0; i < 4; i++) {
    int gi = tid + 256 * i;
    srow[i] = gi >> 3;
    sc4[i] = (gi & 7) * 4;
    vA[i] = (bm + srow[i]) < M;
    pA[i] = X + (size_t)(bm + srow[i]) * FIN + sc4[i];
    pB[i] = W + (size_t)(bn + srow[i]) * FIN + sc4[i];
  }

  for (int k0 = 0; k0 < FIN; k0 += BK) {
#pragma unroll
    for (int i = 0; i < 4; i++) {
      float4 va = vA[i] ? *(const float4*)pA[i] : make_float4(0.f, 0.f, 0.f, 0.f);
      float4 vb = *(const float4*)pB[i];
      pA[i] += BK;
      pB[i] += BK;
      __half2 a0 = __floats2half2_rn(va.x, va.y);
      __half2 a1 = __floats2half2_rn(va.z, va.w);
      *(uint2*)&sA[srow[i]][sc4[i]] = make_uint2(*(uint32_t*)&a0, *(uint32_t*)&a1);
      __half2 b0 = __floats2half2_rn(vb.x, vb.y);
      __half2 b1 = __floats2half2_rn(vb.z, vb.w);
      *(uint2*)&sB[srow[i]][sc4[i]] = make_uint2(*(uint32_t*)&b0, *(uint32_t*)&b1);
    }
    __syncthreads();

#pragma unroll
    for (int k16 = 0; k16 < 2; k16++) {
      const int k = k16 * 16;
      uint32_t a[2][4], bb[4][4];
      ldsm_x4(a[0], sA_base + (uint32_t)(aoff + k) * 2);
      ldsm_x4(a[1], sA_base + (uint32_t)(aoff + 16 * HPITCH + k) * 2);
#pragma unroll
      for (int p = 0; p < 4; p++)
        ldsm_x4(bb[p], sB_base + (uint32_t)(boff + p * 16 * HPITCH + k) * 2);
#pragma unroll
      for (int mt = 0; mt < 2; mt++)
#pragma unroll
        for (int p = 0; p < 4; p++) {
          uint32_t b0[2] = {bb[p][0], bb[p][2]};
          uint32_t b1[2] = {bb[p][1], bb[p][3]};
          mma_f16(acc[mt][2 * p], a[mt], b0);
          mma_f16(acc[mt][2 * p + 1], a[mt], b1);
        }
    }
    __syncthreads();
  }

  // ---- epilogue: + Ws_bias (folded into T), store fp16 (L2-resident), fused exp(Ar) ----
  const uint64_t pol = mk_policy_el();
  const int head = (bn + wn) >> 6;
  float asr[16];
#pragma unroll
  for (int nt = 0; nt < 8; nt++) {
    int colh = nt * 8 + 2 * t;
    asr[nt * 2 + 0] = As[head * 128 + OUTD + colh];
    asr[nt * 2 + 1] = As[head * 128 + OUTD + colh + 1];
  }
  float arsum[4] = {0.f, 0.f, 0.f, 0.f};

#pragma unroll
  for (int mt = 0; mt < 2; mt++) {
    int r0 = bm + wm + mt * 16 + g;
#pragma unroll
    for (int nt = 0; nt < 8; nt++) {
      int c = bn + wn + nt * 8 + 2 * t;
      float wb0 = Wb[c], wb1 = Wb[c + 1];
      float v0 = acc[mt][nt][0] + wb0, v1 = acc[mt][nt][1] + wb1;
      float v2 = acc[mt][nt][2] + wb0, v3 = acc[mt][nt][3] + wb1;
      arsum[mt * 2 + 0] += v0 * asr[nt * 2] + v1 * asr[nt * 2 + 1];
      arsum[mt * 2 + 1] += v2 * asr[nt * 2] + v3 * asr[nt * 2 + 1];
      if (r0 < M) {
        __half2 hv = __floats2half2_rn(v0, v1);
        stg_T_el(&g_T16[(size_t)r0 * HO + c], *(uint32_t*)&hv, pol);
      }
      if (r0 + 8 < M) {
        __half2 hv = __floats2half2_rn(v2, v3);
        stg_T_el(&g_T16[(size_t)(r0 + 8) * HO + c], *(uint32_t*)&hv, pol);
      }
    }
  }
  float bias_r = As_bias[head * 2 + 1];
#pragma unroll
  for (int q = 0; q < 4; q++) {
    float v = arsum[q];
    v += __shfl_xor_sync(0xffffffffu, v, 1);
    v += __shfl_xor_sync(0xffffffffu, v, 2);
    if (t == 0) {
      int r = bm + wm + (q >> 1) * 16 + g + (q & 1) * 8;
      if (r < M) g_Arx[r * HEADS + head] = __expf(v + bias_r);
    }
  }
}

// ---------------- CSR build ----------------
__global__ void count_kernel(const int* __restrict__ row, int E) {
  int e = blockIdx.x * blockDim.x + threadIdx.x;
  if (e < E) atomicAdd(&g_cnt[row[e]], 1);
}

__global__ __launch_bounds__(1024) void scan_blocks_kernel(int N) {
  __shared__ int warpsum[32];
  int tid = threadIdx.x, lane = tid & 31, w = tid >> 5;
  int i = blockIdx.x * 1024 + tid;
  int v = (i < N) ? g_cnt[i] : 0;
#pragma unroll
  for (int o = 1; o < 32; o <<= 1) {
    int u = __shfl_up_sync(0xffffffffu, v, o);
    if (lane >= o) v += u;
  }
  if (lane == 31) warpsum[w] = v;
  __syncthreads();
  if (w == 0) {
    int s = warpsum[lane];
#pragma unroll
    for (int o = 1; o < 32; o <<= 1) {
      int u = __shfl_up_sync(0xffffffffu, s, o);
      if (lane >= o) s += u;
    }
    warpsum[lane] = s;
    if (lane == 31) g_part[blockIdx.x] = s;
  }
  __syncthreads();
  int add = (w > 0) ? warpsum[w - 1] : 0;
  if (i < N) g_off[i + 1] = v + add;
}

__global__ void scan_part_kernel(int nb) {
  int lane = threadIdx.x;
  if (lane == 0) g_off[0] = 0;
  int carry = 0;
  for (int base = 0; base < nb; base += 32) {
    int v = (base + lane < nb) ? g_part[base + lane] : 0;
    int inc = v;
#pragma unroll
    for (int o = 1; o < 32; o <<= 1) {
      int u = __shfl_up_sync(0xffffffffu, inc, o);
      if (lane >= o) inc += u;
    }
    if (base + lane < nb) g_part[base + lane] = carry + inc - v;
    carry += __shfl_sync(0xffffffffu, inc, 31);
  }
}

__global__ void scan_add_kernel(int N) {
  int i = blockIdx.x * blockDim.x + threadIdx.x;
  if (i < N) {
    g_off[i + 1] += g_part[i >> 10];
    g_cnt[i] = 0;  // zero cursors for scatter
  }
}

__global__ void scatter_kernel(const int* __restrict__ row,
                               const int* __restrict__ col, int E) {
  int e = blockIdx.x * blockDim.x + threadIdx.x;
  if (e < E) {
    int r = row[e];
    int p = atomicAdd(&g_cnt[r], 1);
    g_col[g_off[r] + p] = col[e];
  }
}

// ---------------- aggregate: softmax over incoming edges + weighted gather ----------------
// One block/node, warp h = head h. exp precomputed (g_Arx). Pass C: 2 edges per
// warp iteration (lanes 0-15 edge i, lanes 16-31 edge i+1, uint2/lane), unroll 4
// (r11-proven). T loads use evict_last policy; out stores are streaming (.cs).
#define SMAX 256
__global__ __launch_bounds__(256) void agg_kernel(
    const float* __restrict__ Wb, float* __restrict__ out, int N) {
  int n = blockIdx.x;
  int tid = threadIdx.x;
  int h = tid >> 5, l = tid & 31;
  int half = l >> 4, sl = l & 15;
  int s = g_off[n];
  int deg = g_off[n + 1] - s;
  if (tid == 0) g_cnt[n] = 0;  // reset for next replay's count_kernel

  __shared__ float2 sfe[SMAX * 9];  // [i][h]: (exp(score), T-row byte offset)

  const uint64_t pol = mk_policy_el();
  float acc4[4] = {0.f, 0.f, 0.f, 0.f};
  float inv = 0.f;

  if (deg > 0 && deg <= SMAX) {
    // pass A: coalesced exp load + byte offset
    int tot = deg * 8;
    for (int idx = tid; idx < tot; idx += 256) {
      int i = idx >> 3, hh = idx & 7;
      int c = g_col[s + i];
      sfe[i * 9 + hh] = make_float2(g_Arx[c * HEADS + hh], __int_as_float(c * (HO * 2)));
    }
    __syncthreads();

    // pass B: per-head sum of unnormalized alpha
    float sum = 0.f;
    for (int i = l; i < deg; i += 32) sum += sfe[i * 9 + h].x;
#pragma unroll
    for (int o = 16; o; o >>= 1) sum += __shfl_xor_sync(0xffffffffu, sum, o);
    inv = 1.f / sum;

    // pass C: 2 edges per iteration; lane covers 4 cols (8 B) of its edge's slice
    const char* Tb = (const char*)g_T16 + (size_t)h * 128 + (size_t)sl * 8;
    int deg2 = deg & ~1;
#pragma unroll 4
    for (int i = 0; i < deg2; i += 2) {
      float2 fc = sfe[(i + half) * 9 + h];
      uint2 raw = ldg_T_el(Tb + __float_as_int(fc.y), pol);
      float2 f0 = __half22float2(*(__half2*)&raw.x);
      float2 f1 = __half22float2(*(__half2*)&raw.y);
      acc4[0] += fc.x * f0.x;
      acc4[1] += fc.x * f0.y;
      acc4[2] += fc.x * f1.x;
      acc4[3] += fc.x * f1.y;
    }
    if (deg & 1) {
      float2 fc = sfe[deg2 * 9 + h];
      if (half == 0) {
        uint2 raw = ldg_T_el(Tb + __float_as_int(fc.y), pol);
        float2 f0 = __half22float2(*(__half2*)&raw.x);
        float2 f1 = __half22float2(*(__half2*)&raw.y);
        acc4[0] += fc.x * f0.x;
        acc4[1] += fc.x * f0.y;
        acc4[2] += fc.x * f1.x;
        acc4[3] += fc.x * f1.y;
      }
    }
  } else if (deg > SMAX) {
    // fallback for huge degree: stream from global, exps precomputed
    float sum = 0.f;
    for (int i = l; i < deg; i += 32)
      sum += g_Arx[g_col[s + i] * HEADS + h];
#pragma unroll
    for (int o = 16; o; o >>= 1) sum += __shfl_xor_sync(0xffffffffu, sum, o);
    inv = 1.f / sum;
    const char* Tb = (const char*)g_T16 + (size_t)h * 128 + (size_t)sl * 8;
    int deg2 = deg & ~1;
    for (int i = 0; i < deg2; i += 2) {
      int c = g_col[s + i + half];
      float a = g_Arx[c * HEADS + h];
      uint2 raw = ldg_T_el(Tb + (size_t)c * (HO * 2), pol);
      float2 f0 = __half22float2(*(__half2*)&raw.x);
      float2 f1 = __half22float2(*(__half2*)&raw.y);
      acc4[0] += a * f0.x;
      acc4[1] += a * f0.y;
      acc4[2] += a * f1.x;
      acc4[3] += a * f1.y;
    }
    if (deg & 1) {
      int c = g_col[s + deg2];
      float a = g_Arx[c * HEADS + h];
      if (half == 0) {
        uint2 raw = ldg_T_el(Tb + (size_t)c * (HO * 2), pol);
        float2 f0 = __half22float2(*(__half2*)&raw.x);
        float2 f1 = __half22float2(*(__half2*)&raw.y);
        acc4[0] += a * f0.x;
        acc4[1] += a * f0.y;
        acc4[2] += a * f1.x;
        acc4[3] += a * f1.y;
      }
    }
  }

  // combine the two lane-halves; lanes 0-15 of each warp store 4 cols
#pragma unroll
  for (int j = 0; j < 4; j++) acc4[j] += __shfl_xor_sync(0xffffffffu, acc4[j], 16);
  if (half == 0) {
    int oc = h * 64 + 4 * sl;
    float4 r;
    if (deg == 0) {  // T carries Ws_bias and sum(alpha)=1 otherwise
      r.x = Wb[oc]; r.y = Wb[oc + 1]; r.z = Wb[oc + 2]; r.w = Wb[oc + 3];
    } else {
      r.x = acc4[0] * inv; r.y = acc4[1] * inv; r.z = acc4[2] * inv; r.w = acc4[3] * inv;
    }
    r.x = r.x > 0.f ? r.x : expm1f(r.x);
    r.y = r.y > 0.f ? r.y : expm1f(r.y);
    r.z = r.z > 0.f ? r.z : expm1f(r.z);
    r.w = r.w > 0.f ? r.w : expm1f(r.w);
    stg_out_cs(out + (size_t)n * HO + oc, r);
  }
}

// ---------------- launch ----------------
extern "C" void kernel_launch(void* const* d_in, const int* in_sizes, int n_in,
                              void* d_out, int out_size) {
  const float* x        = (const float*)d_in[0];
  const int*   edge_row = (const int*)d_in[1];
  const int*   edge_col = (const int*)d_in[2];
  const float* Ws       = (const float*)d_in[3];
  const float* Ws_bias  = (const float*)d_in[4];
  const float* As       = (const float*)d_in[5];
  const float* As_bias  = (const float*)d_in[6];
  float* out = (float*)d_out;

  const int N = in_sizes[0] / FIN;   // 50000
  const int E = in_sizes[1];         // 1600000

  // one-time stream/event setup (host objects only; no device memory)
  static cudaStream_t s2 = nullptr;
  static cudaEvent_t ev_fork = nullptr, ev_join = nullptr;
  if (s2 == nullptr) {
    cudaStreamCreateWithFlags(&s2, cudaStreamNonBlocking);
    cudaEventCreateWithFlags(&ev_fork, cudaEventDisableTiming);
    cudaEventCreateWithFlags(&ev_join, cudaEventDisableTiming);
  }

  int eb = (E + 255) / 256;
  int nb = (N + 1023) / 1024;

  // fork: CSR build on s2, concurrent with GEMM on the capture stream
  cudaEventRecord(ev_fork, 0);
  cudaStreamWaitEvent(s2, ev_fork, 0);
  count_kernel<<<eb, 256, 0, s2>>>(edge_row, E);
  scan_blocks_kernel<<<nb, 1024, 0, s2>>>(N);
  scan_part_kernel<<<1, 32, 0, s2>>>(nb);

  // main stream: GEMM (4th submission -> profiled by ncu)
  dim3 ggrid((N + BM - 1) / BM, HO / BN);
  gemm_f16_kernel<<<ggrid, 256>>>(x, Ws, Ws_bias, As, As_bias, N);

  scan_add_kernel<<<(N + 255) / 256, 256, 0, s2>>>(N);
  scatter_kernel<<<eb, 256, 0, s2>>>(edge_row, edge_col, E);
  cudaEventRecord(ev_join, s2);

  // join, then softmax + aggregate + ELU
  cudaStreamWaitEvent(0, ev_join, 0);
  agg_kernel<<<N, 256>>>(Ws_bias, out, N);
}

// round 16
// speedup vs baseline: 1.2966x; 1.0197x over previous
#include <cuda_runtime.h>
#include <cuda_bf16.h>
#include <cuda_fp16.h>
#include <math.h>
#include <stdint.h>

// Problem constants (fixed by the reference)
#define NN 50000
#define EE 1600000
#define FIN 256
#define OUTD 64
#define HEADS 8
#define HO 512   // HEADS*OUTD

// ---------------- device scratch (no allocs allowed) ----------------
__device__ __half g_T16[(size_t)NN * HO];  // transformed nodes + bias, fp16 [N, 512]
__device__ float g_Arx[NN * HEADS];        // exp(Ar + bias_r)
__device__ int   g_cnt[NN];                // zero-init; cycle: count->0->cursor->0 (agg)
__device__ int   g_off[NN + 1];
__device__ int   g_col[EE];
__device__ int   g_part[128];

// ---------------- mma / ldmatrix / cache-hint helpers ----------------
__device__ __forceinline__ void mma_f16(float* d, const uint32_t* a, const uint32_t* b) {
  asm volatile(
      "mma.sync.aligned.m16n8k16.row.col.f32.f16.f16.f32 "
      "{%0,%1,%2,%3}, {%4,%5,%6,%7}, {%8,%9}, {%0,%1,%2,%3};"
      : "+f"(d[0]), "+f"(d[1]), "+f"(d[2]), "+f"(d[3])
      : "r"(a[0]), "r"(a[1]), "r"(a[2]), "r"(a[3]), "r"(b[0]), "r"(b[1]));
}

__device__ __forceinline__ void ldsm_x4(uint32_t* r, uint32_t saddr) {
  asm volatile(
      "ldmatrix.sync.aligned.m8n8.x4.shared.b16 {%0,%1,%2,%3}, [%4];"
      : "=r"(r[0]), "=r"(r[1]), "=r"(r[2]), "=r"(r[3])
      : "r"(saddr));
}

// access policy: evict_last for the whole allocation fraction
__device__ __forceinline__ uint64_t mk_policy_el() {
  uint64_t p;
  asm("createpolicy.fractional.L2::evict_last.b64 %0, 1.0;" : "=l"(p));
  return p;
}

// T gather load: keep T lines resident in L2 (evict_last via cache_hint)
__device__ __forceinline__ uint2 ldg_T_el(const void* p, uint64_t pol) {
  uint2 v;
  asm volatile("ld.global.nc.L2::cache_hint.v2.u32 {%0,%1}, [%2], %3;"
               : "=r"(v.x), "=r"(v.y) : "l"(p), "l"(pol));
  return v;
}

// T creation store: born L2-resident
__device__ __forceinline__ void stg_T_el(void* p, uint32_t v, uint64_t pol) {
  asm volatile("st.global.L2::cache_hint.b32 [%0], %1, %2;"
               :: "l"(p), "r"(v), "l"(pol) : "memory");
}

// output store: streaming (evict-first), don't pollute L2
__device__ __forceinline__ void stg_out_cs(void* p, float4 v) {
  asm volatile("st.global.cs.v4.f32 [%0], {%1,%2,%3,%4};"
               :: "l"(p), "f"(v.x), "f"(v.y), "f"(v.z), "f"(v.w) : "memory");
}

// ---------------- GEMM: T = X (M x 256) * W^T + bias -> fp16, fused exp(Ar) ----------------
// 256 threads, 8 warps (4m x 2n), warp tile 32x64. DOUBLE-BUFFERED smem: one
// __syncthreads per k-iter; tile k+1's LDG/STS issue before tile k's MMA chain,
// hiding the global round trip under 32 HMMA + 10 LDSM.
#define BM 128
#define BN 128
#define BK 32
#define HPITCH 40   // halves per smem row (80 B pitch; conflict-free for LDS & LDSM)
#define BUF_HALVES (BM * HPITCH)   // elements per buffer (5120)

__global__ __launch_bounds__(256, 2) void gemm_f16_kernel(
    const float* __restrict__ X, const float* __restrict__ W,
    const float* __restrict__ Wb, const float* __restrict__ As,
    const float* __restrict__ As_bias, int M) {
  __shared__ __half sA[2][BM][HPITCH];
  __shared__ __half sB[2][BN][HPITCH];
  const int bm = blockIdx.x * BM;
  const int bn = blockIdx.y * BN;
  const int tid = threadIdx.x;
  const int wid = tid >> 5, lane = tid & 31;
  const int wm = (wid & 3) * 32;   // warp m offset
  const int wn = (wid >> 2) * 64;  // warp n offset (one head)
  const int g = lane >> 2;
  const int t = lane & 3;

  const int lrow = lane & 15;
  const int lcol = (lane >> 4) * 8;
  const uint32_t sA_base = (uint32_t)__cvta_generic_to_shared(&sA[0][0][0]);
  const uint32_t sB_base = (uint32_t)__cvta_generic_to_shared(&sB[0][0][0]);
  const int aoff = (wm + lrow) * HPITCH + lcol;
  const int boff = (wn + lrow) * HPITCH + lcol;

  float acc[2][8][4];
#pragma unroll
  for (int mt = 0; mt < 2; mt++)
#pragma unroll
    for (int nt = 0; nt < 8; nt++)
#pragma unroll
      for (int j = 0; j < 4; j++) acc[mt][nt][j] = 0.f;

  int srow[4], sc4[4];
  const float* pA[4];
  const float* pB[4];
  bool vA[4];
#pragma unroll
  for (int i = 0; i < 4; i++) {
    int gi = tid + 256 * i;
    srow[i] = gi >> 3;
    sc4[i] = (gi & 7) * 4;
    vA[i] = (bm + srow[i]) < M;
    pA[i] = X + (size_t)(bm + srow[i]) * FIN + sc4[i];
    pB[i] = W + (size_t)(bn + srow[i]) * FIN + sc4[i];
  }

  // preload tile 0 into buffer 0
#pragma unroll
  for (int i = 0; i < 4; i++) {
    float4 va = vA[i] ? *(const float4*)pA[i] : make_float4(0.f, 0.f, 0.f, 0.f);
    float4 vb = *(const float4*)pB[i];
    pA[i] += BK;
    pB[i] += BK;
    __half2 a0 = __floats2half2_rn(va.x, va.y);
    __half2 a1 = __floats2half2_rn(va.z, va.w);
    *(uint2*)&sA[0][srow[i]][sc4[i]] = make_uint2(*(uint32_t*)&a0, *(uint32_t*)&a1);
    __half2 b0 = __floats2half2_rn(vb.x, vb.y);
    __half2 b1 = __floats2half2_rn(vb.z, vb.w);
    *(uint2*)&sB[0][srow[i]][sc4[i]] = make_uint2(*(uint32_t*)&b0, *(uint32_t*)&b1);
  }
  __syncthreads();

#pragma unroll
  for (int it = 0; it < FIN / BK; it++) {
    const int cur = it & 1;
    const int nxt = cur ^ 1;

    // issue next tile's loads/converts/stores FIRST (overlap with MMA below)
    if (it < FIN / BK - 1) {
#pragma unroll
      for (int i = 0; i < 4; i++) {
        float4 va = vA[i] ? *(const float4*)pA[i] : make_float4(0.f, 0.f, 0.f, 0.f);
        float4 vb = *(const float4*)pB[i];
        pA[i] += BK;
        pB[i] += BK;
        __half2 a0 = __floats2half2_rn(va.x, va.y);
        __half2 a1 = __floats2half2_rn(va.z, va.w);
        *(uint2*)&sA[nxt][srow[i]][sc4[i]] = make_uint2(*(uint32_t*)&a0, *(uint32_t*)&a1);
        __half2 b0 = __floats2half2_rn(vb.x, vb.y);
        __half2 b1 = __floats2half2_rn(vb.z, vb.w);
        *(uint2*)&sB[nxt][srow[i]][sc4[i]] = make_uint2(*(uint32_t*)&b0, *(uint32_t*)&b1);
      }
    }

    // MMA over current buffer
    const uint32_t abuf = sA_base + (uint32_t)(cur * BUF_HALVES) * 2;
    const uint32_t bbuf = sB_base + (uint32_t)(cur * BUF_HALVES) * 2;
#pragma unroll
    for (int k16 = 0; k16 < 2; k16++) {
      const int k = k16 * 16;
      uint32_t a[2][4], bb[4][4];
      ldsm_x4(a[0], abuf + (uint32_t)(aoff + k) * 2);
      ldsm_x4(a[1], abuf + (uint32_t)(aoff + 16 * HPITCH + k) * 2);
#pragma unroll
      for (int p = 0; p < 4; p++)
        ldsm_x4(bb[p], bbuf + (uint32_t)(boff + p * 16 * HPITCH + k) * 2);
#pragma unroll
      for (int mt = 0; mt < 2; mt++)
#pragma unroll
        for (int p = 0; p < 4; p++) {
          uint32_t b0[2] = {bb[p][0], bb[p][2]};
          uint32_t b1[2] = {bb[p][1], bb[p][3]};
          mma_f16(acc[mt][2 * p], a[mt], b0);
          mma_f16(acc[mt][2 * p + 1], a[mt], b1);
        }
    }
    __syncthreads();
  }

  // ---- epilogue: + Ws_bias (folded into T), store fp16 (L2-resident), fused exp(Ar) ----
  const uint64_t pol = mk_policy_el();
  const int head = (bn + wn) >> 6;
  float asr[16];
#pragma unroll
  for (int nt = 0; nt < 8; nt++) {
    int colh = nt * 8 + 2 * t;
    asr[nt * 2 + 0] = As[head * 128 + OUTD + colh];
    asr[nt * 2 + 1] = As[head * 128 + OUTD + colh + 1];
  }
  float arsum[4] = {0.f, 0.f, 0.f, 0.f};

#pragma unroll
  for (int mt = 0; mt < 2; mt++) {
    int r0 = bm + wm + mt * 16 + g;
#pragma unroll
    for (int nt = 0; nt < 8; nt++) {
      int c = bn + wn + nt * 8 + 2 * t;
      float wb0 = Wb[c], wb1 = Wb[c + 1];
      float v0 = acc[mt][nt][0] + wb0, v1 = acc[mt][nt][1] + wb1;
      float v2 = acc[mt][nt][2] + wb0, v3 = acc[mt][nt][3] + wb1;
      arsum[mt * 2 + 0] += v0 * asr[nt * 2] + v1 * asr[nt * 2 + 1];
      arsum[mt * 2 + 1] += v2 * asr[nt * 2] + v3 * asr[nt * 2 + 1];
      if (r0 < M) {
        __half2 hv = __floats2half2_rn(v0, v1);
        stg_T_el(&g_T16[(size_t)r0 * HO + c], *(uint32_t*)&hv, pol);
      }
      if (r0 + 8 < M) {
        __half2 hv = __floats2half2_rn(v2, v3);
        stg_T_el(&g_T16[(size_t)(r0 + 8) * HO + c], *(uint32_t*)&hv, pol);
      }
    }
  }
  float bias_r = As_bias[head * 2 + 1];
#pragma unroll
  for (int q = 0; q < 4; q++) {
    float v = arsum[q];
    v += __shfl_xor_sync(0xffffffffu, v, 1);
    v += __shfl_xor_sync(0xffffffffu, v, 2);
    if (t == 0) {
      int r = bm + wm + (q >> 1) * 16 + g + (q & 1) * 8;
      if (r < M) g_Arx[r * HEADS + head] = __expf(v + bias_r);
    }
  }
}

// ---------------- CSR build ----------------
__global__ void count_kernel(const int* __restrict__ row, int E) {
  int e = blockIdx.x * blockDim.x + threadIdx.x;
  if (e < E) atomicAdd(&g_cnt[row[e]], 1);
}

__global__ __launch_bounds__(1024) void scan_blocks_kernel(int N) {
  __shared__ int warpsum[32];
  int tid = threadIdx.x, lane = tid & 31, w = tid >> 5;
  int i = blockIdx.x * 1024 + tid;
  int v = (i < N) ? g_cnt[i] : 0;
#pragma unroll
  for (int o = 1; o < 32; o <<= 1) {
    int u = __shfl_up_sync(0xffffffffu, v, o);
    if (lane >= o) v += u;
  }
  if (lane == 31) warpsum[w] = v;
  __syncthreads();
  if (w == 0) {
    int s = warpsum[lane];
#pragma unroll
    for (int o = 1; o < 32; o <<= 1) {
      int u = __shfl_up_sync(0xffffffffu, s, o);
      if (lane >= o) s += u;
    }
    warpsum[lane] = s;
    if (lane == 31) g_part[blockIdx.x] = s;
  }
  __syncthreads();
  int add = (w > 0) ? warpsum[w - 1] : 0;
  if (i < N) g_off[i + 1] = v + add;
}

__global__ void scan_part_kernel(int nb) {
  int lane = threadIdx.x;
  if (lane == 0) g_off[0] = 0;
  int carry = 0;
  for (int base = 0; base < nb; base += 32) {
    int v = (base + lane < nb) ? g_part[base + lane] : 0;
    int inc = v;
#pragma unroll
    for (int o = 1; o < 32; o <<= 1) {
      int u = __shfl_up_sync(0xffffffffu, inc, o);
      if (lane >= o) inc += u;
    }
    if (base + lane < nb) g_part[base + lane] = carry + inc - v;
    carry += __shfl_sync(0xffffffffu, inc, 31);
  }
}

__global__ void scan_add_kernel(int N) {
  int i = blockIdx.x * blockDim.x + threadIdx.x;
  if (i < N) {
    g_off[i + 1] += g_part[i >> 10];
    g_cnt[i] = 0;  // zero cursors for scatter
  }
}

__global__ void scatter_kernel(const int* __restrict__ row,
                               const int* __restrict__ col, int E) {
  int e = blockIdx.x * blockDim.x + threadIdx.x;
  if (e < E) {
    int r = row[e];
    int p = atomicAdd(&g_cnt[r], 1);
    g_col[g_off[r] + p] = col[e];
  }
}

// ---------------- aggregate: softmax over incoming edges + weighted gather ----------------
// (FROZEN at r15-best: 2 edges/iter, unroll 4, evict_last T loads, .cs out stores.)
#define SMAX 256
__global__ __launch_bounds__(256) void agg_kernel(
    const float* __restrict__ Wb, float* __restrict__ out, int N) {
  int n = blockIdx.x;
  int tid = threadIdx.x;
  int h = tid >> 5, l = tid & 31;
  int half = l >> 4, sl = l & 15;
  int s = g_off[n];
  int deg = g_off[n + 1] - s;
  if (tid == 0) g_cnt[n] = 0;  // reset for next replay's count_kernel

  __shared__ float2 sfe[SMAX * 9];  // [i][h]: (exp(score), T-row byte offset)

  const uint64_t pol = mk_policy_el();
  float acc4[4] = {0.f, 0.f, 0.f, 0.f};
  float inv = 0.f;

  if (deg > 0 && deg <= SMAX) {
    // pass A: coalesced exp load + byte offset
    int tot = deg * 8;
    for (int idx = tid; idx < tot; idx += 256) {
      int i = idx >> 3, hh = idx & 7;
      int c = g_col[s + i];
      sfe[i * 9 + hh] = make_float2(g_Arx[c * HEADS + hh], __int_as_float(c * (HO * 2)));
    }
    __syncthreads();

    // pass B: per-head sum of unnormalized alpha
    float sum = 0.f;
    for (int i = l; i < deg; i += 32) sum += sfe[i * 9 + h].x;
#pragma unroll
    for (int o = 16; o; o >>= 1) sum += __shfl_xor_sync(0xffffffffu, sum, o);
    inv = 1.f / sum;

    // pass C: 2 edges per iteration; lane covers 4 cols (8 B) of its edge's slice
    const char* Tb = (const char*)g_T16 + (size_t)h * 128 + (size_t)sl * 8;
    int deg2 = deg & ~1;
#pragma unroll 4
    for (int i = 0; i < deg2; i += 2) {
      float2 fc = sfe[(i + half) * 9 + h];
      uint2 raw = ldg_T_el(Tb + __float_as_int(fc.y), pol);
      float2 f0 = __half22float2(*(__half2*)&raw.x);
      float2 f1 = __half22float2(*(__half2*)&raw.y);
      acc4[0] += fc.x * f0.x;
      acc4[1] += fc.x * f0.y;
      acc4[2] += fc.x * f1.x;
      acc4[3] += fc.x * f1.y;
    }
    if (deg & 1) {
      float2 fc = sfe[deg2 * 9 + h];
      if (half == 0) {
        uint2 raw = ldg_T_el(Tb + __float_as_int(fc.y), pol);
        float2 f0 = __half22float2(*(__half2*)&raw.x);
        float2 f1 = __half22float2(*(__half2*)&raw.y);
        acc4[0] += fc.x * f0.x;
        acc4[1] += fc.x * f0.y;
        acc4[2] += fc.x * f1.x;
        acc4[3] += fc.x * f1.y;
      }
    }
  } else if (deg > SMAX) {
    // fallback for huge degree: stream from global, exps precomputed
    float sum = 0.f;
    for (int i = l; i < deg; i += 32)
      sum += g_Arx[g_col[s + i] * HEADS + h];
#pragma unroll
    for (int o = 16; o; o >>= 1) sum += __shfl_xor_sync(0xffffffffu, sum, o);
    inv = 1.f / sum;
    const char* Tb = (const char*)g_T16 + (size_t)h * 128 + (size_t)sl * 8;
    int deg2 = deg & ~1;
    for (int i = 0; i < deg2; i += 2) {
      int c = g_col[s + i + half];
      float a = g_Arx[c * HEADS + h];
      uint2 raw = ldg_T_el(Tb + (size_t)c * (HO * 2), pol);
      float2 f0 = __half22float2(*(__half2*)&raw.x);
      float2 f1 = __half22float2(*(__half2*)&raw.y);
      acc4[0] += a * f0.x;
      acc4[1] += a * f0.y;
      acc4[2] += a * f1.x;
      acc4[3] += a * f1.y;
    }
    if (deg & 1) {
      int c = g_col[s + deg2];
      float a = g_Arx[c * HEADS + h];
      if (half == 0) {
        uint2 raw = ldg_T_el(Tb + (size_t)c * (HO * 2), pol);
        float2 f0 = __half22float2(*(__half2*)&raw.x);
        float2 f1 = __half22float2(*(__half2*)&raw.y);
        acc4[0] += a * f0.x;
        acc4[1] += a * f0.y;
        acc4[2] += a * f1.x;
        acc4[3] += a * f1.y;
      }
    }
  }

  // combine the two lane-halves; lanes 0-15 of each warp store 4 cols
#pragma unroll
  for (int j = 0; j < 4; j++) acc4[j] += __shfl_xor_sync(0xffffffffu, acc4[j], 16);
  if (half == 0) {
    int oc = h * 64 + 4 * sl;
    float4 r;
    if (deg == 0) {  // T carries Ws_bias and sum(alpha)=1 otherwise
      r.x = Wb[oc]; r.y = Wb[oc + 1]; r.z = Wb[oc + 2]; r.w = Wb[oc + 3];
    } else {
      r.x = acc4[0] * inv; r.y = acc4[1] * inv; r.z = acc4[2] * inv; r.w = acc4[3] * inv;
    }
    r.x = r.x > 0.f ? r.x : expm1f(r.x);
    r.y = r.y > 0.f ? r.y : expm1f(r.y);
    r.z = r.z > 0.f ? r.z : expm1f(r.z);
    r.w = r.w > 0.f ? r.w : expm1f(r.w);
    stg_out_cs(out + (size_t)n * HO + oc, r);
  }
}

// ---------------- launch ----------------
extern "C" void kernel_launch(void* const* d_in, const int* in_sizes, int n_in,
                              void* d_out, int out_size) {
  const float* x        = (const float*)d_in[0];
  const int*   edge_row = (const int*)d_in[1];
  const int*   edge_col = (const int*)d_in[2];
  const float* Ws       = (const float*)d_in[3];
  const float* Ws_bias  = (const float*)d_in[4];
  const float* As       = (const float*)d_in[5];
  const float* As_bias  = (const float*)d_in[6];
  float* out = (float*)d_out;

  const int N = in_sizes[0] / FIN;   // 50000
  const int E = in_sizes[1];         // 1600000

  // one-time stream/event setup (host objects only; no device memory)
  static cudaStream_t s2 = nullptr;
  static cudaEvent_t ev_fork = nullptr, ev_join = nullptr;
  if (s2 == nullptr) {
    cudaStreamCreateWithFlags(&s2, cudaStreamNonBlocking);
    cudaEventCreateWithFlags(&ev_fork, cudaEventDisableTiming);
    cudaEventCreateWithFlags(&ev_join, cudaEventDisableTiming);
  }

  int eb = (E + 255) / 256;
  int nb = (N + 1023) / 1024;

  // fork: CSR build on s2, concurrent with GEMM on the capture stream
  cudaEventRecord(ev_fork, 0);
  cudaStreamWaitEvent(s2, ev_fork, 0);
  count_kernel<<<eb, 256, 0, s2>>>(edge_row, E);
  scan_blocks_kernel<<<nb, 1024, 0, s2>>>(N);
  scan_part_kernel<<<1, 32, 0, s2>>>(nb);

  // main stream: GEMM (4th submission -> profiled by ncu)
  dim3 ggrid((N + BM - 1) / BM, HO / BN);
  gemm_f16_kernel<<<ggrid, 256>>>(x, Ws, Ws_bias, As, As_bias, N);

  scan_add_kernel<<<(N + 255) / 256, 256, 0, s2>>>(N);
  scatter_kernel<<<eb, 256, 0, s2>>>(edge_row, edge_col, E);
  cudaEventRecord(ev_join, s2);

  // join, then softmax + aggregate + ELU
  cudaStreamWaitEvent(0, ev_join, 0);
  agg_kernel<<<N, 256>>>(Ws_bias, out, N);
}